// round 15
// baseline (speedup 1.0000x reference)
#include <cuda_runtime.h>

#define Bn 16
#define Qn 64
#define Kn 1024
#define Dn 256
#define Hn 128

// Scratch (device globals: no allocation allowed).
// Zero-initialized at module load; dead splits (k0 >= vlen[b]) are never
// written (vlen constant across replays), so they contribute exact zeros.
__device__ float g_qp[Bn*Qn*Hn];       // projected queries  [B,Q,H]
__device__ float g_kp[Bn*Kn*Hn];       // projected keys     [B,K,H]
#define KS 16
#define OKS (Kn/KS)                    // 64 k per split
__device__ float g_part[KS*Bn*Qn*Dn];  // output partials [KS][B,Q,D]
__device__ float g_psum[KS*Bn*Qn];     // per-split exp row sums [KS][B*Q]

// ---------- packed f32x2 helpers (Blackwell) ----------
__device__ __forceinline__ unsigned long long pack2(float x, float y){
    unsigned long long r; asm("mov.b64 %0, {%1,%2};" : "=l"(r) : "f"(x), "f"(y)); return r;
}
__device__ __forceinline__ unsigned long long fma2(unsigned long long a, unsigned long long b, unsigned long long c){
    unsigned long long d; asm("fma.rn.f32x2 %0, %1, %2, %3;" : "=l"(d) : "l"(a), "l"(b), "l"(c)); return d;
}
__device__ __forceinline__ void unpack2(unsigned long long v, float& lo, float& hi){
    asm("mov.b64 {%0,%1}, %2;" : "=f"(lo), "=f"(hi) : "l"(v));
}
__device__ __forceinline__ float tanh_fast(float x){
    float y; asm("tanh.approx.f32 %0, %1;" : "=f"(y) : "f"(x)); return y;
}

// ---------------- projection (q and k fused; dead k-rows skipped) ----------------
// 512 threads: thread owns h = t&127, row-quarter rh = t>>7 (8 of 32 rows).
// Grid unchanged; warps per live block doubled to beat the live-blocks/SM cap.
// W loads front-batched 8-deep (MLP 8) to cover L2 latency.
#define PR 32    // rows per block
#define PT 512   // threads
#define XS 36    // padded smem row stride (floats); 144B, 16B-aligned
#define WB 8     // W load batch depth
#define QBLOCKS ((Bn*Qn)/PR)   // 32
#define KBLOCKS ((Bn*Kn)/PR)   // 512

__global__ __launch_bounds__(PT) void proj_kernel(const float* __restrict__ Xq,
                                                  const float* __restrict__ Wq,
                                                  const float* __restrict__ Xk,
                                                  const float* __restrict__ Wk,
                                                  const int* __restrict__ vlen){
    __shared__ float xs[Dn*XS];   // X tile transposed: xs[d][r]
    const float* X; const float* W; float* out; int row0;
    if (blockIdx.x < QBLOCKS){ X = Xq; W = Wq; out = g_qp; row0 = blockIdx.x * PR; }
    else {
        X = Xk; W = Wk; out = g_kp;
        row0 = (blockIdx.x - QBLOCKS) * PR;
        if ((row0 & (Kn-1)) >= vlen[row0 >> 10]) return;   // dead kp rows
    }
    const int t = threadIdx.x;

    for (int i = t; i < PR*Dn; i += PT){
        int r = i >> 8;          // /256
        int d = i & (Dn-1);
        xs[d*XS + r] = X[(row0 + r)*Dn + d];
    }
    __syncthreads();

    const int h  = t & 127;      // output column
    const int rh = t >> 7;       // row quarter 0..3 (warp-uniform)
    const float* Wh = W + h;

    unsigned long long acc[4];   // 8 rows as 4 f32x2 pairs
#pragma unroll
    for (int i = 0; i < 4; i++) acc[i] = 0ull;

    for (int db = 0; db < Dn; db += WB){
        float wb[WB];                              // front-batched: MLP=8
#pragma unroll
        for (int i = 0; i < WB; i++) wb[i] = Wh[(db + i)*Hn];
#pragma unroll
        for (int i = 0; i < WB; i++){
            unsigned long long w2 = pack2(wb[i], wb[i]);
            const ulonglong2* xp =
                reinterpret_cast<const ulonglong2*>(&xs[(db + i)*XS + rh*8]);
#pragma unroll
            for (int m = 0; m < 2; m++){
                ulonglong2 xv = xp[m];             // warp-uniform LDS.128 broadcast
                acc[2*m]   = fma2(w2, xv.x, acc[2*m]);
                acc[2*m+1] = fma2(w2, xv.y, acc[2*m+1]);
            }
        }
    }
    float* outr = out + (size_t)(row0 + rh*8)*Hn + h;
#pragma unroll
    for (int i = 0; i < 4; i++){
        float lo, hi; unpack2(acc[i], lo, hi);
        outr[(2*i    )*Hn] = lo;
        outr[(2*i + 1)*Hn] = hi;
    }
}

// ------- fused score+out: one block = (16q x 64k) tile of one batch -------
// Phase 1: exps of tanh-scores into SMEM (fp32 MUFU tanh; no max shift:
// |s| <= sum|w_v| ~ 9, exp in [1e-7,1e4], exact in fp32).
// Phase 2: V accumulation from SMEM exps -> g_part + g_psum.
// Dead splits (k0 >= v) write NOTHING (stay zero from static init).
#define FQT 16    // q per block
#define FT  256
#define ASTR 20   // padded exp-tile row stride (floats): 80B, 16B-aligned
#define VB 16     // V load batch

__global__ __launch_bounds__(FT) void fused_kernel(const float* __restrict__ V,
                                                   const float* __restrict__ wv,
                                                   const int* __restrict__ vlen){
    const int qt = blockIdx.x;    // 0..3
    const int kz = blockIdx.y;    // 0..KS-1
    const int b  = blockIdx.z;
    const int v  = vlen[b];
    const int k0 = kz * OKS;
    if (k0 >= v) return;                      // dead split
    const int q0 = qt * FQT;
    const int t  = threadIdx.x;
    const int kmax = min(OKS, v - k0);

    __shared__ float ks[OKS*Hn];   // kp tile, swizzled 512B rows (32KB)
    __shared__ float qs[FQT*Hn];   // q tile (8KB)
    __shared__ float ws[Hn];
    __shared__ float es[OKS*ASTR]; // exp tile: es[k*ASTR + q] (5KB)

    if (t < Hn) ws[t] = wv[t];
    const float* kpb = g_kp + (size_t)(b*Kn + k0)*Hn;
    for (int i = t; i < OKS*Hn; i += FT){
        int j = i >> 7, h = i & 127;
        int sidx = j*Hn + ((((h>>2) ^ (j & 7))) << 2) + (h & 3);
        ks[sidx] = kpb[i];
    }
    const float* qpb = g_qp + (size_t)(b*Qn + q0)*Hn;
    for (int i = t; i < FQT*Hn; i += FT) qs[i] = qpb[i];
    __syncthreads();

    // ---- phase 1: scores -> exp in SMEM ----
    {
        const int lane = t & 31;
        const int wrp  = t >> 5;          // 0..7
        const int kh   = wrp & 1;         // k half
        const int qb   = (wrp >> 1) << 2; // q base 0,4,8,12 (warp-uniform)
        const int k    = kh*32 + lane;
        const int jx   = lane & 7;        // swizzle key (= k & 7)

        float a0 = 0.f, a1 = 0.f, a2 = 0.f, a3 = 0.f;
#pragma unroll 8
        for (int c = 0; c < Hn/4; c++){
            float4 kv = *reinterpret_cast<const float4*>(&ks[k*Hn + ((c ^ jx) << 2)]);
            float4 w4 = *reinterpret_cast<const float4*>(&ws[c << 2]);
            float4 q0v = *reinterpret_cast<const float4*>(&qs[(qb  )*Hn + (c << 2)]);
            float4 q1v = *reinterpret_cast<const float4*>(&qs[(qb+1)*Hn + (c << 2)]);
            float4 q2v = *reinterpret_cast<const float4*>(&qs[(qb+2)*Hn + (c << 2)]);
            float4 q3v = *reinterpret_cast<const float4*>(&qs[(qb+3)*Hn + (c << 2)]);
            a0 += w4.x*tanh_fast(q0v.x+kv.x) + w4.y*tanh_fast(q0v.y+kv.y)
                + w4.z*tanh_fast(q0v.z+kv.z) + w4.w*tanh_fast(q0v.w+kv.w);
            a1 += w4.x*tanh_fast(q1v.x+kv.x) + w4.y*tanh_fast(q1v.y+kv.y)
                + w4.z*tanh_fast(q1v.z+kv.z) + w4.w*tanh_fast(q1v.w+kv.w);
            a2 += w4.x*tanh_fast(q2v.x+kv.x) + w4.y*tanh_fast(q2v.y+kv.y)
                + w4.z*tanh_fast(q2v.z+kv.z) + w4.w*tanh_fast(q2v.w+kv.w);
            a3 += w4.x*tanh_fast(q3v.x+kv.x) + w4.y*tanh_fast(q3v.y+kv.y)
                + w4.z*tanh_fast(q3v.z+kv.z) + w4.w*tanh_fast(q3v.w+kv.w);
        }
        const bool live = (k < kmax);
        es[k*ASTR + qb    ] = live ? __expf(a0) : 0.f;
        es[k*ASTR + qb + 1] = live ? __expf(a1) : 0.f;
        es[k*ASTR + qb + 2] = live ? __expf(a2) : 0.f;
        es[k*ASTR + qb + 3] = live ? __expf(a3) : 0.f;
    }
    __syncthreads();

    // ---- phase 2: V accumulation ----
    const int d2 = t & 127;       // d-pair index
    const int qh = t >> 7;        // q-half (warp-uniform)
    const float2* Vt = reinterpret_cast<const float2*>(V + ((size_t)b*Kn + k0)*Dn) + d2;

    unsigned long long accA[4];   // (q2r,q2r+1) x d0 within this half
    unsigned long long accB[4];   // (q2r,q2r+1) x d1
#pragma unroll
    for (int r = 0; r < 4; r++){ accA[r] = 0ull; accB[r] = 0ull; }

#pragma unroll
    for (int gb = 0; gb < OKS/VB; gb++){
        float2 vb[VB];                             // front-batched: MLP=16
#pragma unroll
        for (int i = 0; i < VB; i++) vb[i] = Vt[(size_t)(gb*VB + i)*(Dn/2)];
#pragma unroll
        for (int i = 0; i < VB; i++){
            int k = gb*VB + i;
            unsigned long long v0 = pack2(vb[i].x, vb[i].x);
            unsigned long long v1 = pack2(vb[i].y, vb[i].y);
            const ulonglong2* ap = reinterpret_cast<const ulonglong2*>(&es[k*ASTR]) + 2*qh;
            ulonglong2 a0 = ap[0];    // q = qh*8 + 0..3, broadcast
            ulonglong2 a1 = ap[1];    // q = qh*8 + 4..7
            accA[0] = fma2(a0.x, v0, accA[0]);  accB[0] = fma2(a0.x, v1, accB[0]);
            accA[1] = fma2(a0.y, v0, accA[1]);  accB[1] = fma2(a0.y, v1, accB[1]);
            accA[2] = fma2(a1.x, v0, accA[2]);  accB[2] = fma2(a1.x, v1, accB[2]);
            accA[3] = fma2(a1.y, v0, accA[3]);  accB[3] = fma2(a1.y, v1, accB[3]);
        }
    }

    float* part = g_part + ((size_t)kz*Bn*Qn + b*Qn + q0 + qh*8)*Dn;
#pragma unroll
    for (int r = 0; r < 4; r++){
        float fa, fb, ga, gb2;
        unpack2(accA[r], fa, fb);
        unpack2(accB[r], ga, gb2);
        reinterpret_cast<float2*>(part + (2*r  )*Dn)[d2] = make_float2(fa, ga);
        reinterpret_cast<float2*>(part + (2*r+1)*Dn)[d2] = make_float2(fb, gb2);
    }

    // per-q exp sums of this split (smem unchanged since phase 1; sync done above)
    if (t < FQT*8){
        int q = t >> 3, j = t & 7;
        float s = 0.f;
#pragma unroll
        for (int i = 0; i < 8; i++) s += es[(j*8 + i)*ASTR + q];
#pragma unroll
        for (int o = 4; o > 0; o >>= 1) s += __shfl_down_sync(0xffffffffu, s, o, 8);
        if (j == 0) g_psum[kz*(Bn*Qn) + b*Qn + q0 + q] = s;
    }
}

// ------- reduce: out = (1/sum psum) * sum_{live} part -------
// One block per (b,q) row; nz block-uniform, dead splits never read.
#define RT 256
#define NOUT4 ((Bn*Qn*Dn)/4)   // 65536 float4
#define RI 64                  // i4 values per block = one (b,q) row

__global__ __launch_bounds__(RT) void reduce_kernel(const int* __restrict__ vlen,
                                                    float* __restrict__ out){
    const int t   = threadIdx.x;
    const int li  = t & (RI-1);
    const int zq  = t >> 6;                   // 0..3 (warp-uniform)
    const int i4  = blockIdx.x * RI + li;
    const int row = blockIdx.x;               // one (b,q) row per block
    const int b   = row >> 6;
    const int nz  = (vlen[b] + OKS - 1) >> 6; // live splits, block-uniform

    const float4* p = reinterpret_cast<const float4*>(g_part);
    float4 x[4];
    float  ps[4];
#pragma unroll
    for (int j = 0; j < 4; j++){              // only live splits touched
        int z = zq*4 + j;
        if (z < nz){
            x[j]  = p[(size_t)z*NOUT4 + i4];
            ps[j] = g_psum[z*(Bn*Qn) + row];
        } else {
            x[j]  = make_float4(0.f, 0.f, 0.f, 0.f);
            ps[j] = 0.f;
        }
    }
    x[0].x += x[1].x; x[0].y += x[1].y; x[0].z += x[1].z; x[0].w += x[1].w;
    x[2].x += x[3].x; x[2].y += x[3].y; x[2].z += x[3].z; x[2].w += x[3].w;
    x[0].x += x[2].x; x[0].y += x[2].y; x[0].z += x[2].z; x[0].w += x[2].w;
    ps[0] += ps[1]; ps[2] += ps[3]; ps[0] += ps[2];

    __shared__ float4 sx[3][RI];
    __shared__ float  sp[3][RI];
    if (zq){ sx[zq-1][li] = x[0]; sp[zq-1][li] = ps[0]; }
    __syncthreads();
    if (zq == 0){
        float4 s = x[0];
        float sm = ps[0];
#pragma unroll
        for (int g = 0; g < 3; g++){
            float4 o = sx[g][li];
            s.x += o.x; s.y += o.y; s.z += o.z; s.w += o.w;
            sm += sp[g][li];
        }
        const float inv = __fdividef(1.f, sm);
        s.x *= inv; s.y *= inv; s.z *= inv; s.w *= inv;
        reinterpret_cast<float4*>(out)[i4] = s;
    }
}

// ---------------- launch ----------------
extern "C" void kernel_launch(void* const* d_in, const int* in_sizes, int n_in,
                              void* d_out, int out_size){
    const float* queries = (const float*)d_in[0];
    const float* keys    = (const float*)d_in[1];
    const float* values  = (const float*)d_in[2];
    const int*   vlen    = (const int*)  d_in[3];
    const float* W_q     = (const float*)d_in[4];
    const float* W_k     = (const float*)d_in[5];
    const float* w_v     = (const float*)d_in[6];
    float* out = (float*)d_out;

    proj_kernel<<<QBLOCKS + KBLOCKS, PT>>>(queries, W_q, keys, W_k, vlen);  // 544 blocks
    fused_kernel<<<dim3(Qn/FQT, KS, Bn), FT>>>(values, w_v, vlen);          // 1024 blocks
    reduce_kernel<<<NOUT4/RI, RT>>>(vlen, out);                             // 1024 blocks
}

// round 16
// speedup vs baseline: 1.0984x; 1.0984x over previous
#include <cuda_runtime.h>

#define Bn 16
#define Qn 64
#define Kn 1024
#define Dn 256
#define Hn 128

// Scratch (device globals: no allocation allowed).
// Zero-initialized at module load; dead splits (k0 >= vlen[b]) are never
// written (vlen constant across replays), so they contribute exact zeros.
__device__ float g_qp[Bn*Qn*Hn];       // projected queries  [B,Q,H]
__device__ float g_kp[Bn*Kn*Hn];       // projected keys     [B,K,H]
#define KS 16
#define OKS (Kn/KS)                    // 64 k per split
__device__ float g_part[KS*Bn*Qn*Dn];  // output partials [KS][B,Q,D]
__device__ float g_psum[KS*Bn*Qn];     // per-split exp row sums [KS][B*Q]

// ---------- packed f32x2 helpers (Blackwell) ----------
__device__ __forceinline__ unsigned long long pack2(float x, float y){
    unsigned long long r; asm("mov.b64 %0, {%1,%2};" : "=l"(r) : "f"(x), "f"(y)); return r;
}
__device__ __forceinline__ unsigned long long fma2(unsigned long long a, unsigned long long b, unsigned long long c){
    unsigned long long d; asm("fma.rn.f32x2 %0, %1, %2, %3;" : "=l"(d) : "l"(a), "l"(b), "l"(c)); return d;
}
__device__ __forceinline__ void unpack2(unsigned long long v, float& lo, float& hi){
    asm("mov.b64 {%0,%1}, %2;" : "=f"(lo), "=f"(hi) : "l"(v));
}
__device__ __forceinline__ float tanh_fast(float x){
    float y; asm("tanh.approx.f32 %0, %1;" : "=f"(y) : "f"(x)); return y;
}

// ---------------- projection (q and k fused; dead k-rows skipped) ----------------
// PR=16 rows/block doubles the live-block count (occupancy via grid shape),
// keeping R14's per-warp instruction mix. Thread owns h = t&127, row-half
// rh = t>>7 (8 rows). W loads front-batched 8-deep (MLP 8).
#define PR 16    // rows per block
#define PT 256   // threads
#define XS 20    // padded smem row stride (floats); 80B, 16B-aligned
#define WB 8     // W load batch depth
#define QBLOCKS ((Bn*Qn)/PR)   // 64
#define KBLOCKS ((Bn*Kn)/PR)   // 1024

__global__ __launch_bounds__(PT) void proj_kernel(const float* __restrict__ Xq,
                                                  const float* __restrict__ Wq,
                                                  const float* __restrict__ Xk,
                                                  const float* __restrict__ Wk,
                                                  const int* __restrict__ vlen){
    __shared__ float xs[Dn*XS];   // X tile transposed: xs[d][r] (20KB)
    const float* X; const float* W; float* out; int row0;
    if (blockIdx.x < QBLOCKS){ X = Xq; W = Wq; out = g_qp; row0 = blockIdx.x * PR; }
    else {
        X = Xk; W = Wk; out = g_kp;
        row0 = (blockIdx.x - QBLOCKS) * PR;
        if ((row0 & (Kn-1)) >= vlen[row0 >> 10]) return;   // dead kp rows
    }
    const int t = threadIdx.x;

    for (int i = t; i < PR*Dn; i += PT){
        int r = i >> 8;          // /256
        int d = i & (Dn-1);
        xs[d*XS + r] = X[(row0 + r)*Dn + d];
    }
    __syncthreads();

    const int h  = t & 127;      // output column
    const int rh = t >> 7;       // row half 0..1 (warp-uniform)
    const float* Wh = W + h;

    unsigned long long acc[4];   // 8 rows as 4 f32x2 pairs
#pragma unroll
    for (int i = 0; i < 4; i++) acc[i] = 0ull;

    for (int db = 0; db < Dn; db += WB){
        float wb[WB];                              // front-batched: MLP=8
#pragma unroll
        for (int i = 0; i < WB; i++) wb[i] = Wh[(db + i)*Hn];
#pragma unroll
        for (int i = 0; i < WB; i++){
            unsigned long long w2 = pack2(wb[i], wb[i]);
            const ulonglong2* xp =
                reinterpret_cast<const ulonglong2*>(&xs[(db + i)*XS + rh*8]);
#pragma unroll
            for (int m = 0; m < 2; m++){
                ulonglong2 xv = xp[m];             // warp-uniform LDS.128 broadcast
                acc[2*m]   = fma2(w2, xv.x, acc[2*m]);
                acc[2*m+1] = fma2(w2, xv.y, acc[2*m+1]);
            }
        }
    }
    float* outr = out + (size_t)(row0 + rh*8)*Hn + h;
#pragma unroll
    for (int i = 0; i < 4; i++){
        float lo, hi; unpack2(acc[i], lo, hi);
        outr[(2*i    )*Hn] = lo;
        outr[(2*i + 1)*Hn] = hi;
    }
}

// ------- fused score+out: one block = (16q x 64k) tile of one batch -------
// Phase 1: exps of tanh-scores into SMEM (fp32 MUFU tanh; no max shift:
// |s| <= sum|w_v| ~ 9, exp in [1e-7,1e4], exact in fp32).
// Phase 2: V accumulation from SMEM exps -> g_part + g_psum.
// Dead splits (k0 >= v) write NOTHING (stay zero from static init).
#define FQT 16    // q per block
#define FT  256
#define ASTR 20   // padded exp-tile row stride (floats): 80B, 16B-aligned
#define VB 16     // V load batch

__global__ __launch_bounds__(FT) void fused_kernel(const float* __restrict__ V,
                                                   const float* __restrict__ wv,
                                                   const int* __restrict__ vlen){
    const int qt = blockIdx.x;    // 0..3
    const int kz = blockIdx.y;    // 0..KS-1
    const int b  = blockIdx.z;
    const int v  = vlen[b];
    const int k0 = kz * OKS;
    if (k0 >= v) return;                      // dead split
    const int q0 = qt * FQT;
    const int t  = threadIdx.x;
    const int kmax = min(OKS, v - k0);

    __shared__ float ks[OKS*Hn];   // kp tile, swizzled 512B rows (32KB)
    __shared__ float qs[FQT*Hn];   // q tile (8KB)
    __shared__ float ws[Hn];
    __shared__ float es[OKS*ASTR]; // exp tile: es[k*ASTR + q] (5KB)

    if (t < Hn) ws[t] = wv[t];
    const float* kpb = g_kp + (size_t)(b*Kn + k0)*Hn;
    for (int i = t; i < OKS*Hn; i += FT){
        int j = i >> 7, h = i & 127;
        int sidx = j*Hn + ((((h>>2) ^ (j & 7))) << 2) + (h & 3);
        ks[sidx] = kpb[i];
    }
    const float* qpb = g_qp + (size_t)(b*Qn + q0)*Hn;
    for (int i = t; i < FQT*Hn; i += FT) qs[i] = qpb[i];
    __syncthreads();

    // ---- phase 1: scores -> exp in SMEM ----
    {
        const int lane = t & 31;
        const int wrp  = t >> 5;          // 0..7
        const int kh   = wrp & 1;         // k half
        const int qb   = (wrp >> 1) << 2; // q base 0,4,8,12 (warp-uniform)
        const int k    = kh*32 + lane;
        const int jx   = lane & 7;        // swizzle key (= k & 7)

        float a0 = 0.f, a1 = 0.f, a2 = 0.f, a3 = 0.f;
#pragma unroll 8
        for (int c = 0; c < Hn/4; c++){
            float4 kv = *reinterpret_cast<const float4*>(&ks[k*Hn + ((c ^ jx) << 2)]);
            float4 w4 = *reinterpret_cast<const float4*>(&ws[c << 2]);
            float4 q0v = *reinterpret_cast<const float4*>(&qs[(qb  )*Hn + (c << 2)]);
            float4 q1v = *reinterpret_cast<const float4*>(&qs[(qb+1)*Hn + (c << 2)]);
            float4 q2v = *reinterpret_cast<const float4*>(&qs[(qb+2)*Hn + (c << 2)]);
            float4 q3v = *reinterpret_cast<const float4*>(&qs[(qb+3)*Hn + (c << 2)]);
            a0 += w4.x*tanh_fast(q0v.x+kv.x) + w4.y*tanh_fast(q0v.y+kv.y)
                + w4.z*tanh_fast(q0v.z+kv.z) + w4.w*tanh_fast(q0v.w+kv.w);
            a1 += w4.x*tanh_fast(q1v.x+kv.x) + w4.y*tanh_fast(q1v.y+kv.y)
                + w4.z*tanh_fast(q1v.z+kv.z) + w4.w*tanh_fast(q1v.w+kv.w);
            a2 += w4.x*tanh_fast(q2v.x+kv.x) + w4.y*tanh_fast(q2v.y+kv.y)
                + w4.z*tanh_fast(q2v.z+kv.z) + w4.w*tanh_fast(q2v.w+kv.w);
            a3 += w4.x*tanh_fast(q3v.x+kv.x) + w4.y*tanh_fast(q3v.y+kv.y)
                + w4.z*tanh_fast(q3v.z+kv.z) + w4.w*tanh_fast(q3v.w+kv.w);
        }
        const bool live = (k < kmax);
        es[k*ASTR + qb    ] = live ? __expf(a0) : 0.f;
        es[k*ASTR + qb + 1] = live ? __expf(a1) : 0.f;
        es[k*ASTR + qb + 2] = live ? __expf(a2) : 0.f;
        es[k*ASTR + qb + 3] = live ? __expf(a3) : 0.f;
    }
    __syncthreads();

    // ---- phase 2: V accumulation ----
    const int d2 = t & 127;       // d-pair index
    const int qh = t >> 7;        // q-half (warp-uniform)
    const float2* Vt = reinterpret_cast<const float2*>(V + ((size_t)b*Kn + k0)*Dn) + d2;

    unsigned long long accA[4];   // (q2r,q2r+1) x d0 within this half
    unsigned long long accB[4];   // (q2r,q2r+1) x d1
#pragma unroll
    for (int r = 0; r < 4; r++){ accA[r] = 0ull; accB[r] = 0ull; }

#pragma unroll
    for (int gb = 0; gb < OKS/VB; gb++){
        float2 vb[VB];                             // front-batched: MLP=16
#pragma unroll
        for (int i = 0; i < VB; i++) vb[i] = Vt[(size_t)(gb*VB + i)*(Dn/2)];
#pragma unroll
        for (int i = 0; i < VB; i++){
            int k = gb*VB + i;
            unsigned long long v0 = pack2(vb[i].x, vb[i].x);
            unsigned long long v1 = pack2(vb[i].y, vb[i].y);
            const ulonglong2* ap = reinterpret_cast<const ulonglong2*>(&es[k*ASTR]) + 2*qh;
            ulonglong2 a0 = ap[0];    // q = qh*8 + 0..3, broadcast
            ulonglong2 a1 = ap[1];    // q = qh*8 + 4..7
            accA[0] = fma2(a0.x, v0, accA[0]);  accB[0] = fma2(a0.x, v1, accB[0]);
            accA[1] = fma2(a0.y, v0, accA[1]);  accB[1] = fma2(a0.y, v1, accB[1]);
            accA[2] = fma2(a1.x, v0, accA[2]);  accB[2] = fma2(a1.x, v1, accB[2]);
            accA[3] = fma2(a1.y, v0, accA[3]);  accB[3] = fma2(a1.y, v1, accB[3]);
        }
    }

    float* part = g_part + ((size_t)kz*Bn*Qn + b*Qn + q0 + qh*8)*Dn;
#pragma unroll
    for (int r = 0; r < 4; r++){
        float fa, fb, ga, gb2;
        unpack2(accA[r], fa, fb);
        unpack2(accB[r], ga, gb2);
        reinterpret_cast<float2*>(part + (2*r  )*Dn)[d2] = make_float2(fa, ga);
        reinterpret_cast<float2*>(part + (2*r+1)*Dn)[d2] = make_float2(fb, gb2);
    }

    // per-q exp sums of this split (smem unchanged since phase 1; sync done above)
    if (t < FQT*8){
        int q = t >> 3, j = t & 7;
        float s = 0.f;
#pragma unroll
        for (int i = 0; i < 8; i++) s += es[(j*8 + i)*ASTR + q];
#pragma unroll
        for (int o = 4; o > 0; o >>= 1) s += __shfl_down_sync(0xffffffffu, s, o, 8);
        if (j == 0) g_psum[kz*(Bn*Qn) + b*Qn + q0 + q] = s;
    }
}

// ------- reduce: out = (1/sum psum) * sum_{live} part -------
// One block per (b,q) row; nz block-uniform, dead splits never read.
#define RT 256
#define NOUT4 ((Bn*Qn*Dn)/4)   // 65536 float4
#define RI 64                  // i4 values per block = one (b,q) row

__global__ __launch_bounds__(RT) void reduce_kernel(const int* __restrict__ vlen,
                                                    float* __restrict__ out){
    const int t   = threadIdx.x;
    const int li  = t & (RI-1);
    const int zq  = t >> 6;                   // 0..3 (warp-uniform)
    const int i4  = blockIdx.x * RI + li;
    const int row = blockIdx.x;               // one (b,q) row per block
    const int b   = row >> 6;
    const int nz  = (vlen[b] + OKS - 1) >> 6; // live splits, block-uniform

    const float4* p = reinterpret_cast<const float4*>(g_part);
    float4 x[4];
    float  ps[4];
#pragma unroll
    for (int j = 0; j < 4; j++){              // only live splits touched
        int z = zq*4 + j;
        if (z < nz){
            x[j]  = p[(size_t)z*NOUT4 + i4];
            ps[j] = g_psum[z*(Bn*Qn) + row];
        } else {
            x[j]  = make_float4(0.f, 0.f, 0.f, 0.f);
            ps[j] = 0.f;
        }
    }
    x[0].x += x[1].x; x[0].y += x[1].y; x[0].z += x[1].z; x[0].w += x[1].w;
    x[2].x += x[3].x; x[2].y += x[3].y; x[2].z += x[3].z; x[2].w += x[3].w;
    x[0].x += x[2].x; x[0].y += x[2].y; x[0].z += x[2].z; x[0].w += x[2].w;
    ps[0] += ps[1]; ps[2] += ps[3]; ps[0] += ps[2];

    __shared__ float4 sx[3][RI];
    __shared__ float  sp[3][RI];
    if (zq){ sx[zq-1][li] = x[0]; sp[zq-1][li] = ps[0]; }
    __syncthreads();
    if (zq == 0){
        float4 s = x[0];
        float sm = ps[0];
#pragma unroll
        for (int g = 0; g < 3; g++){
            float4 o = sx[g][li];
            s.x += o.x; s.y += o.y; s.z += o.z; s.w += o.w;
            sm += sp[g][li];
        }
        const float inv = __fdividef(1.f, sm);
        s.x *= inv; s.y *= inv; s.z *= inv; s.w *= inv;
        reinterpret_cast<float4*>(out)[i4] = s;
    }
}

// ---------------- launch ----------------
extern "C" void kernel_launch(void* const* d_in, const int* in_sizes, int n_in,
                              void* d_out, int out_size){
    const float* queries = (const float*)d_in[0];
    const float* keys    = (const float*)d_in[1];
    const float* values  = (const float*)d_in[2];
    const int*   vlen    = (const int*)  d_in[3];
    const float* W_q     = (const float*)d_in[4];
    const float* W_k     = (const float*)d_in[5];
    const float* w_v     = (const float*)d_in[6];
    float* out = (float*)d_out;

    proj_kernel<<<QBLOCKS + KBLOCKS, PT>>>(queries, W_q, keys, W_k, vlen);  // 1088 blocks
    fused_kernel<<<dim3(Qn/FQT, KS, Bn), FT>>>(values, w_v, vlen);          // 1024 blocks
    reduce_kernel<<<NOUT4/RI, RT>>>(vlen, out);                             // 1024 blocks
}

// round 17
// speedup vs baseline: 1.3767x; 1.2534x over previous
#include <cuda_runtime.h>

#define Bn 16
#define Qn 64
#define Kn 1024
#define Dn 256
#define Hn 128

// Scratch (device globals: no allocation allowed).
// Zero-initialized at module load; dead splits/rows are never written
// (vlen constant across replays), so they contribute exact zeros.
__device__ float g_qp[Bn*Qn*Hn];       // projected queries  [B,Q,H]
__device__ float g_kp[Bn*Kn*Hn];       // projected keys     [B,K,H]
#define KS 16
#define OKS (Kn/KS)                    // 64 k per split
__device__ float g_part[KS*Bn*Qn*Dn];  // output partials [KS][B,Q,D]
__device__ float g_psum[KS*Bn*Qn];     // per-split exp row sums [KS][B*Q]

// ---------- packed f32x2 helpers (Blackwell) ----------
__device__ __forceinline__ unsigned long long pack2(float x, float y){
    unsigned long long r; asm("mov.b64 %0, {%1,%2};" : "=l"(r) : "f"(x), "f"(y)); return r;
}
__device__ __forceinline__ unsigned long long fma2(unsigned long long a, unsigned long long b, unsigned long long c){
    unsigned long long d; asm("fma.rn.f32x2 %0, %1, %2, %3;" : "=l"(d) : "l"(a), "l"(b), "l"(c)); return d;
}
__device__ __forceinline__ void unpack2(unsigned long long v, float& lo, float& hi){
    asm("mov.b64 {%0,%1}, %2;" : "=f"(lo), "=f"(hi) : "l"(v));
}
__device__ __forceinline__ float tanh_fast(float x){
    float y; asm("tanh.approx.f32 %0, %1;" : "=f"(y) : "f"(x)); return y;
}

// ---------------- projection: dense live-tile enumeration ----------------
// Items: [0, QITEMS) are q-tiles; [QITEMS, QITEMS + sum(ceil(v[b]/PR))) are
// LIVE k-tiles (prefix over vlen computed per block). Live bids are
// contiguous -> round-robin placement balances live blocks across SMs.
// Thread layout: PT=128; thread owns 2 h-columns (h2, h2+64) x 8 rows.
// Per d: 2 LDG + 2 LDS.128 + 8 fma2 (LSU-lean).
#define PR 16    // rows per tile
#define PT 128   // threads
#define XS 20    // padded smem row stride (floats); 80B, 16B-aligned
#define WB 8     // W load batch depth
#define QITEMS ((Bn*Qn)/PR)          // 64
#define PGRID (QITEMS + (Bn*Kn)/PR)  // 1088 (worst case all live)

__global__ __launch_bounds__(PT) void proj_kernel(const float* __restrict__ Xq,
                                                  const float* __restrict__ Wq,
                                                  const float* __restrict__ Xk,
                                                  const float* __restrict__ Wk,
                                                  const int* __restrict__ vlen){
    __shared__ float xs[Dn*XS];   // X tile transposed: xs[d][r] (20KB)
    __shared__ int sch[Bn+1];     // k-item prefix
    const int t = threadIdx.x;

    if (t == 0){
        int acc = 0;
        sch[0] = 0;
#pragma unroll
        for (int b = 0; b < Bn; b++){ acc += (vlen[b] + PR - 1) >> 4; sch[b+1] = acc; }
    }
    __syncthreads();
    const int total = QITEMS + sch[Bn];
    const int item = blockIdx.x;
    if (item >= total) return;                 // block-uniform exit

    const float* X; const float* W; float* out; int row0;
    if (item < QITEMS){ X = Xq; W = Wq; out = g_qp; row0 = item * PR; }
    else {
        int ki = item - QITEMS;
        int b = 0;
        while (sch[b+1] <= ki) b++;            // <=16 iters, smem-hot
        X = Xk; W = Wk; out = g_kp;
        row0 = b*Kn + (ki - sch[b])*PR;
    }

    for (int i = t; i < PR*Dn; i += PT){
        int r = i >> 8;          // /256
        int d = i & (Dn-1);
        xs[d*XS + r] = X[(row0 + r)*Dn + d];
    }
    __syncthreads();

    const int h2 = t & 63;       // columns h2 and h2+64
    const int rh = t >> 6;       // row half 0..1 (warp-uniform)
    const float* Wa = W + h2;
    const float* Wb = W + h2 + 64;

    unsigned long long accA[4];  // 8 rows (4 f32x2 pairs), col h2
    unsigned long long accB[4];  // 8 rows, col h2+64
#pragma unroll
    for (int i = 0; i < 4; i++){ accA[i] = 0ull; accB[i] = 0ull; }

    for (int db = 0; db < Dn; db += WB){
        float wa[WB], wb[WB];                  // front-batched: MLP=16
#pragma unroll
        for (int i = 0; i < WB; i++){ wa[i] = Wa[(db+i)*Hn]; wb[i] = Wb[(db+i)*Hn]; }
#pragma unroll
        for (int i = 0; i < WB; i++){
            unsigned long long wa2 = pack2(wa[i], wa[i]);
            unsigned long long wb2 = pack2(wb[i], wb[i]);
            const ulonglong2* xp =
                reinterpret_cast<const ulonglong2*>(&xs[(db+i)*XS + rh*8]);
            ulonglong2 x01 = xp[0];            // rows 0..3 of half (broadcast)
            ulonglong2 x23 = xp[1];            // rows 4..7
            accA[0] = fma2(wa2, x01.x, accA[0]);  accB[0] = fma2(wb2, x01.x, accB[0]);
            accA[1] = fma2(wa2, x01.y, accA[1]);  accB[1] = fma2(wb2, x01.y, accB[1]);
            accA[2] = fma2(wa2, x23.x, accA[2]);  accB[2] = fma2(wb2, x23.x, accB[2]);
            accA[3] = fma2(wa2, x23.y, accA[3]);  accB[3] = fma2(wb2, x23.y, accB[3]);
        }
    }
    float* outr = out + (size_t)(row0 + rh*8)*Hn;
#pragma unroll
    for (int i = 0; i < 4; i++){
        float la, ha, lb, hb;
        unpack2(accA[i], la, ha);   // rows 2i, 2i+1 at col h2
        unpack2(accB[i], lb, hb);   // rows 2i, 2i+1 at col h2+64
        outr[(2*i    )*Hn + h2     ] = la;
        outr[(2*i + 1)*Hn + h2     ] = ha;
        outr[(2*i    )*Hn + h2 + 64] = lb;
        outr[(2*i + 1)*Hn + h2 + 64] = hb;
    }
}

// ------- fused score+out: one block = (16q x 64k) tile of one batch -------
// Phase 1: exps of tanh-scores into SMEM (fp32 MUFU tanh; no max shift:
// |s| <= sum|w_v| ~ 9, exp in [1e-7,1e4], exact in fp32).
// Phase 2: V accumulation from SMEM exps -> g_part + g_psum.
// Dead splits (k0 >= v) write NOTHING (stay zero from static init).
#define FQT 16    // q per block
#define FT  256
#define ASTR 20   // padded exp-tile row stride (floats): 80B, 16B-aligned
#define VB 16     // V load batch

__global__ __launch_bounds__(FT) void fused_kernel(const float* __restrict__ V,
                                                   const float* __restrict__ wv,
                                                   const int* __restrict__ vlen){
    const int qt = blockIdx.x;    // 0..3
    const int kz = blockIdx.y;    // 0..KS-1
    const int b  = blockIdx.z;
    const int v  = vlen[b];
    const int k0 = kz * OKS;
    if (k0 >= v) return;                      // dead split
    const int q0 = qt * FQT;
    const int t  = threadIdx.x;
    const int kmax = min(OKS, v - k0);

    __shared__ float ks[OKS*Hn];   // kp tile, swizzled 512B rows (32KB)
    __shared__ float qs[FQT*Hn];   // q tile (8KB)
    __shared__ float ws[Hn];
    __shared__ float es[OKS*ASTR]; // exp tile: es[k*ASTR + q] (5KB)

    if (t < Hn) ws[t] = wv[t];
    const float* kpb = g_kp + (size_t)(b*Kn + k0)*Hn;
    for (int i = t; i < OKS*Hn; i += FT){
        int j = i >> 7, h = i & 127;
        int sidx = j*Hn + ((((h>>2) ^ (j & 7))) << 2) + (h & 3);
        ks[sidx] = kpb[i];
    }
    const float* qpb = g_qp + (size_t)(b*Qn + q0)*Hn;
    for (int i = t; i < FQT*Hn; i += FT) qs[i] = qpb[i];
    __syncthreads();

    // ---- phase 1: scores -> exp in SMEM ----
    {
        const int lane = t & 31;
        const int wrp  = t >> 5;          // 0..7
        const int kh   = wrp & 1;         // k half
        const int qb   = (wrp >> 1) << 2; // q base 0,4,8,12 (warp-uniform)
        const int k    = kh*32 + lane;
        const int jx   = lane & 7;        // swizzle key (= k & 7)

        float a0 = 0.f, a1 = 0.f, a2 = 0.f, a3 = 0.f;
#pragma unroll 8
        for (int c = 0; c < Hn/4; c++){
            float4 kv = *reinterpret_cast<const float4*>(&ks[k*Hn + ((c ^ jx) << 2)]);
            float4 w4 = *reinterpret_cast<const float4*>(&ws[c << 2]);
            float4 q0v = *reinterpret_cast<const float4*>(&qs[(qb  )*Hn + (c << 2)]);
            float4 q1v = *reinterpret_cast<const float4*>(&qs[(qb+1)*Hn + (c << 2)]);
            float4 q2v = *reinterpret_cast<const float4*>(&qs[(qb+2)*Hn + (c << 2)]);
            float4 q3v = *reinterpret_cast<const float4*>(&qs[(qb+3)*Hn + (c << 2)]);
            a0 += w4.x*tanh_fast(q0v.x+kv.x) + w4.y*tanh_fast(q0v.y+kv.y)
                + w4.z*tanh_fast(q0v.z+kv.z) + w4.w*tanh_fast(q0v.w+kv.w);
            a1 += w4.x*tanh_fast(q1v.x+kv.x) + w4.y*tanh_fast(q1v.y+kv.y)
                + w4.z*tanh_fast(q1v.z+kv.z) + w4.w*tanh_fast(q1v.w+kv.w);
            a2 += w4.x*tanh_fast(q2v.x+kv.x) + w4.y*tanh_fast(q2v.y+kv.y)
                + w4.z*tanh_fast(q2v.z+kv.z) + w4.w*tanh_fast(q2v.w+kv.w);
            a3 += w4.x*tanh_fast(q3v.x+kv.x) + w4.y*tanh_fast(q3v.y+kv.y)
                + w4.z*tanh_fast(q3v.z+kv.z) + w4.w*tanh_fast(q3v.w+kv.w);
        }
        const bool live = (k < kmax);
        es[k*ASTR + qb    ] = live ? __expf(a0) : 0.f;
        es[k*ASTR + qb + 1] = live ? __expf(a1) : 0.f;
        es[k*ASTR + qb + 2] = live ? __expf(a2) : 0.f;
        es[k*ASTR + qb + 3] = live ? __expf(a3) : 0.f;
    }
    __syncthreads();

    // ---- phase 2: V accumulation ----
    const int d2 = t & 127;       // d-pair index
    const int qh = t >> 7;        // q-half (warp-uniform)
    const float2* Vt = reinterpret_cast<const float2*>(V + ((size_t)b*Kn + k0)*Dn) + d2;

    unsigned long long accA[4];   // (q2r,q2r+1) x d0 within this half
    unsigned long long accB[4];   // (q2r,q2r+1) x d1
#pragma unroll
    for (int r = 0; r < 4; r++){ accA[r] = 0ull; accB[r] = 0ull; }

#pragma unroll
    for (int gb = 0; gb < OKS/VB; gb++){
        float2 vb[VB];                             // front-batched: MLP=16
#pragma unroll
        for (int i = 0; i < VB; i++) vb[i] = Vt[(size_t)(gb*VB + i)*(Dn/2)];
#pragma unroll
        for (int i = 0; i < VB; i++){
            int k = gb*VB + i;
            unsigned long long v0 = pack2(vb[i].x, vb[i].x);
            unsigned long long v1 = pack2(vb[i].y, vb[i].y);
            const ulonglong2* ap = reinterpret_cast<const ulonglong2*>(&es[k*ASTR]) + 2*qh;
            ulonglong2 a0 = ap[0];    // q = qh*8 + 0..3, broadcast
            ulonglong2 a1 = ap[1];    // q = qh*8 + 4..7
            accA[0] = fma2(a0.x, v0, accA[0]);  accB[0] = fma2(a0.x, v1, accB[0]);
            accA[1] = fma2(a0.y, v0, accA[1]);  accB[1] = fma2(a0.y, v1, accB[1]);
            accA[2] = fma2(a1.x, v0, accA[2]);  accB[2] = fma2(a1.x, v1, accB[2]);
            accA[3] = fma2(a1.y, v0, accA[3]);  accB[3] = fma2(a1.y, v1, accB[3]);
        }
    }

    float* part = g_part + ((size_t)kz*Bn*Qn + b*Qn + q0 + qh*8)*Dn;
#pragma unroll
    for (int r = 0; r < 4; r++){
        float fa, fb, ga, gb2;
        unpack2(accA[r], fa, fb);
        unpack2(accB[r], ga, gb2);
        reinterpret_cast<float2*>(part + (2*r  )*Dn)[d2] = make_float2(fa, ga);
        reinterpret_cast<float2*>(part + (2*r+1)*Dn)[d2] = make_float2(fb, gb2);
    }

    // per-q exp sums of this split (smem unchanged since phase 1; sync done above)
    if (t < FQT*8){
        int q = t >> 3, j = t & 7;
        float s = 0.f;
#pragma unroll
        for (int i = 0; i < 8; i++) s += es[(j*8 + i)*ASTR + q];
#pragma unroll
        for (int o = 4; o > 0; o >>= 1) s += __shfl_down_sync(0xffffffffu, s, o, 8);
        if (j == 0) g_psum[kz*(Bn*Qn) + b*Qn + q0 + q] = s;
    }
}

// ------- reduce: out = (1/sum psum) * sum_{live} part -------
// One block per (b,q) row; nz block-uniform, dead splits never read.
#define RT 256
#define NOUT4 ((Bn*Qn*Dn)/4)   // 65536 float4
#define RI 64                  // i4 values per block = one (b,q) row

__global__ __launch_bounds__(RT) void reduce_kernel(const int* __restrict__ vlen,
                                                    float* __restrict__ out){
    const int t   = threadIdx.x;
    const int li  = t & (RI-1);
    const int zq  = t >> 6;                   // 0..3 (warp-uniform)
    const int i4  = blockIdx.x * RI + li;
    const int row = blockIdx.x;               // one (b,q) row per block
    const int b   = row >> 6;
    const int nz  = (vlen[b] + OKS - 1) >> 6; // live splits, block-uniform

    const float4* p = reinterpret_cast<const float4*>(g_part);
    float4 x[4];
    float  ps[4];
#pragma unroll
    for (int j = 0; j < 4; j++){              // only live splits touched
        int z = zq*4 + j;
        if (z < nz){
            x[j]  = p[(size_t)z*NOUT4 + i4];
            ps[j] = g_psum[z*(Bn*Qn) + row];
        } else {
            x[j]  = make_float4(0.f, 0.f, 0.f, 0.f);
            ps[j] = 0.f;
        }
    }
    x[0].x += x[1].x; x[0].y += x[1].y; x[0].z += x[1].z; x[0].w += x[1].w;
    x[2].x += x[3].x; x[2].y += x[3].y; x[2].z += x[3].z; x[2].w += x[3].w;
    x[0].x += x[2].x; x[0].y += x[2].y; x[0].z += x[2].z; x[0].w += x[2].w;
    ps[0] += ps[1]; ps[2] += ps[3]; ps[0] += ps[2];

    __shared__ float4 sx[3][RI];
    __shared__ float  sp[3][RI];
    if (zq){ sx[zq-1][li] = x[0]; sp[zq-1][li] = ps[0]; }
    __syncthreads();
    if (zq == 0){
        float4 s = x[0];
        float sm = ps[0];
#pragma unroll
        for (int g = 0; g < 3; g++){
            float4 o = sx[g][li];
            s.x += o.x; s.y += o.y; s.z += o.z; s.w += o.w;
            sm += sp[g][li];
        }
        const float inv = __fdividef(1.f, sm);
        s.x *= inv; s.y *= inv; s.z *= inv; s.w *= inv;
        reinterpret_cast<float4*>(out)[i4] = s;
    }
}

// ---------------- launch ----------------
extern "C" void kernel_launch(void* const* d_in, const int* in_sizes, int n_in,
                              void* d_out, int out_size){
    const float* queries = (const float*)d_in[0];
    const float* keys    = (const float*)d_in[1];
    const float* values  = (const float*)d_in[2];
    const int*   vlen    = (const int*)  d_in[3];
    const float* W_q     = (const float*)d_in[4];
    const float* W_k     = (const float*)d_in[5];
    const float* w_v     = (const float*)d_in[6];
    float* out = (float*)d_out;

    proj_kernel<<<PGRID, PT>>>(queries, W_q, keys, W_k, vlen);              // 1088 blocks
    fused_kernel<<<dim3(Qn/FQT, KS, Bn), FT>>>(values, w_v, vlen);          // 1024 blocks
    reduce_kernel<<<NOUT4/RI, RT>>>(vlen, out);                             // 1024 blocks
}